// round 7
// baseline (speedup 1.0000x reference)
#include <cuda_runtime.h>
#include <math.h>
#include <stdint.h>

// Problem constants
#define BT   128          // B*T
#define NP   256          // patches
#define DV   1024         // D_VISION
#define NHD  16           // N_BRANCHES * N_HEADS
#define NBR  4
#define DB   256          // D_BRANCH
#define SCALE 0.125f      // HEAD_DIM^-0.5

#define CH    8           // patches per chunk (main kernel)
#define NCH   32          // chunks per bt
#define CHBYTES (CH * DV * 4)   // 32768

typedef unsigned long long u64;

// -------- device scratch (no allocation allowed) --------
__device__ __align__(16) float g_wqg[NHD * DV];
__device__ float g_gw [NHD];
__device__ float g_scb[NHD];
__device__ __align__(16) float g_y[(size_t)NHD * BT * DV];   // 8 MB
__device__ __align__(16) float g_pooled[NBR * BT * DB];
__device__ float g_sims[BT * 6];

// ---------------- f32x2 helpers ----------------
__device__ __forceinline__ u64 fma2(u64 a, u64 b, u64 c) {
    u64 d;
    asm("fma.rn.f32x2 %0, %1, %2, %3;" : "=l"(d) : "l"(a), "l"(b), "l"(c));
    return d;
}
__device__ __forceinline__ u64 mul2(u64 a, u64 b) {
    u64 d;
    asm("mul.rn.f32x2 %0, %1, %2;" : "=l"(d) : "l"(a), "l"(b));
    return d;
}
__device__ __forceinline__ u64 add2(u64 a, u64 b) {
    u64 d;
    asm("add.rn.f32x2 %0, %1, %2;" : "=l"(d) : "l"(a), "l"(b));
    return d;
}
__device__ __forceinline__ u64 dup2(float v) {
    u64 r;
    asm("mov.b64 %0, {%1, %1};" : "=l"(r) : "f"(v));
    return r;
}
__device__ __forceinline__ u64 pack2(float lo, float hi) {
    u64 r;
    asm("mov.b64 %0, {%1, %2};" : "=l"(r) : "f"(lo), "f"(hi));
    return r;
}
__device__ __forceinline__ void unpack2(u64 v, float& lo, float& hi) {
    asm("mov.b64 {%0, %1}, %2;" : "=f"(lo), "=f"(hi) : "l"(v));
}

// ---------------- sync / bulk-copy helpers ----------------
__device__ __forceinline__ uint32_t smem_u32(const void* p) {
    uint32_t a;
    asm("{ .reg .u64 t; cvta.to.shared.u64 t, %1; cvt.u32.u64 %0, t; }"
        : "=r"(a) : "l"(p));
    return a;
}
__device__ __forceinline__ void mbar_init(uint32_t mbar, uint32_t count) {
    asm volatile("mbarrier.init.shared.b64 [%0], %1;" :: "r"(mbar), "r"(count) : "memory");
}
__device__ __forceinline__ void mbar_expect(uint32_t mbar, uint32_t bytes) {
    asm volatile("mbarrier.arrive.expect_tx.shared.b64 _, [%0], %1;"
                 :: "r"(mbar), "r"(bytes) : "memory");
}
__device__ __forceinline__ void mbar_wait(uint32_t mbar, int phase) {
    asm volatile(
        "{\n\t.reg .pred P;\n\t"
        "WL_%=:\n\t"
        "mbarrier.try_wait.parity.acquire.cta.shared::cta.b64 P, [%0], %1, 0x989680;\n\t"
        "@P bra.uni WD_%=;\n\t"
        "bra.uni WL_%=;\n\t"
        "WD_%=:\n\t}"
        :: "r"(mbar), "r"(phase) : "memory");
}
__device__ __forceinline__ void bulk_g2s(uint32_t dst, const void* src,
                                         uint32_t bytes, uint32_t mbar) {
    asm volatile(
        "cp.async.bulk.shared::cluster.global.mbarrier::complete_tx::bytes [%0], [%1], %2, [%3];"
        :: "r"(dst), "l"(src), "r"(bytes), "r"(mbar) : "memory");
}
__device__ __forceinline__ void nbar_sync(int id, int cnt) {
    asm volatile("bar.sync %0, %1;" :: "r"(id), "r"(cnt) : "memory");
}
__device__ __forceinline__ void nbar_arrive(int id, int cnt) {
    asm volatile("bar.arrive %0, %1;" :: "r"(id), "r"(cnt) : "memory");
}

// =============================================================
// Kernel A: fold query into Wk (+ layernorm affine folding)
// =============================================================
__global__ void prep_kernel(const float* __restrict__ Wk,
                            const float* __restrict__ query,
                            const float* __restrict__ bk,
                            const float* __restrict__ gamma,
                            const float* __restrict__ beta) {
    const int nh = blockIdx.x;
    const int n = nh >> 2, h = nh & 3;
    __shared__ float q_s[64];
    __shared__ float r1[256], r2[256];
    const int t = threadIdx.x;
    if (t < 64) q_s[t] = query[(n * 4 + h) * 64 + t];
    __syncthreads();

    float gw_part = 0.f, bw_part = 0.f;
    const float4* qq = (const float4*)q_s;
    for (int d = t; d < DV; d += 256) {
        const float4* w4 = (const float4*)(Wk + ((size_t)(n * DV + d)) * DB + h * 64);
        float s = 0.f;
        #pragma unroll
        for (int j = 0; j < 16; j++) {
            float4 a = w4[j]; float4 b = qq[j];
            s += a.x * b.x + a.y * b.y + a.z * b.z + a.w * b.w;
        }
        g_wqg[nh * DV + d] = SCALE * gamma[d] * s;
        gw_part += gamma[d] * s;
        bw_part += beta[d] * s;
    }
    r1[t] = gw_part; r2[t] = bw_part;
    __syncthreads();
    for (int s = 128; s; s >>= 1) {
        if (t < s) { r1[t] += r1[t + s]; r2[t] += r2[t + s]; }
        __syncthreads();
    }
    if (t == 0) {
        float bq = 0.f;
        for (int j = 0; j < 64; j++) bq += bk[n * DB + h * 64 + j] * q_s[j];
        g_gw[nh]  = SCALE * r1[0];
        g_scb[nh] = SCALE * (r2[0] + bq);
    }
}

// =============================================================
// Kernel B v6: warp-specialized pipelined main, 512 threads.
//  Group D (warps 0-7): dots (4 rows x d-half per warp) + LN stats
//    partials + online softmax; produces ar2c/f2s per chunk.
//  Group Y (warps 8-15): yacc accumulate (4 cols/thread) + epilogue.
//  Triple-buffered x (CH=8), Y reissues TMA(k+3) after draining.
//  Named barriers: 1 = D-internal, 2 = Y-internal,
//    3 = D->Y "chunk k ready", 4 = Y->D "buffers free", 5 = D->Y state.
// =============================================================
// smem layout (float idx):
//  0    mbar[3] (u64)           -> 8
//  8    f2s[2][16]              -> 40
//  40   mrow[16]                -> 56
//  56   invsr[16]               -> 72
//  72   ccrow[16]               -> 88
//  88   avn[4]                  -> 92  (pad ->96)
//  96   sstat[2][8][2] float2   -> 160
//  160  ar2c[2][8][16]          -> 416
//  416  av[4][256]              -> 1440
//  1440 sc [16][256]            -> 5536
//  5536 scP[16][256]            -> 9632
//  9632 buf[3][8*1024]          -> 34208
#define SMEM_MAIN_FLOATS 34208
#define SMEM_MAIN_BYTES  (SMEM_MAIN_FLOATS * 4)

__global__ void __launch_bounds__(512, 1)
main_kernel(const float* __restrict__ frame,
            const float* __restrict__ gamma,
            const float* __restrict__ beta) {
    extern __shared__ float smf[];
    float* f2s   = smf + 8;      // [2][16]
    float* mrow  = smf + 40;
    float* invsr = smf + 56;
    float* ccrow = smf + 72;
    float* avn   = smf + 88;
    float* sstat = smf + 96;     // [2][8][2] float2
    float* ar2c  = smf + 160;    // [2][8][16]
    float* av    = smf + 416;
    float* sc    = smf + 1440;   // [16][256]
    float* scP   = smf + 5536;   // [16][256]
    float* buf   = smf + 9632;   // [3][8192]

    const int t = threadIdx.x, w = t >> 5, lane = t & 31;
    const int bt = blockIdx.x;
    const uint32_t sbase = smem_u32(smf);
    const uint32_t bufu = smem_u32(buf);

    if (t == 0) {
        mbar_init(sbase + 0, 1);
        mbar_init(sbase + 8, 1);
        mbar_init(sbase + 16, 1);
    }
    __syncthreads();

    const char* src = (const char*)(frame + (size_t)bt * NP * DV);
    if (t == 0) {
        #pragma unroll
        for (int i = 0; i < 3; i++) {
            mbar_expect(sbase + 8 * i, CHBYTES);
            bulk_g2s(bufu + i * CHBYTES, src + (size_t)i * CHBYTES, CHBYTES, sbase + 8 * i);
        }
    }

    if (t < 256) {
        // ============== GROUP D: dots + stats + softmax ==============
        const int rg = w & 3, dh = w >> 2;
        const int rbase = rg * 4;

        // weights: 4 rows x 512 d (this warp's half) = 8 u64/row
        u64 wR[4][8];
        #pragma unroll
        for (int rr = 0; rr < 4; rr++) {
            const ulonglong2* wp =
                (const ulonglong2*)(g_wqg + (rbase + rr) * DV + dh * 512);
            #pragma unroll
            for (int c = 0; c < 4; c++) {
                ulonglong2 v = wp[c * 32 + lane];
                wR[rr][2*c] = v.x; wR[rr][2*c+1] = v.y;
            }
        }

        const int half = lane >> 4, srow = 2 * w + half, pl = lane & 15;
        const float gwS = g_gw[srow], sbS = g_scb[srow];
        const bool ok = pl < CH;
        float mO = -1e30f, sO = 0.f, cpO = 0.f;

        const bool b16 = (lane & 16) != 0;
        const bool b8  = (lane & 8)  != 0;
        const bool b4  = (lane & 4)  != 0;

        for (int kc = 0; kc < NCH; kc++) {
            mbar_wait(sbase + 8 * (kc % 3), (kc / 3) & 1);
            const float* xb = buf + (kc % 3) * (CH * DV);
            const ulonglong2* x2 = (const ulonglong2*)xb;

            // ---- dots (raw, this d-half) + fused LN partial stats ----
            #pragma unroll
            for (int pp = 0; pp < 4; pp++) {
                const int p0 = 2 * pp, p1 = p0 + 1;
                const ulonglong2* r0 = x2 + p0 * 256 + dh * 128;
                const ulonglong2* r1 = x2 + p1 * 256 + dh * 128;
                const bool doStats = (pp == rg);
                u64 a[8];
                #pragma unroll
                for (int i = 0; i < 8; i++) a[i] = 0ull;
                float s0 = 0.f, ss0 = 0.f, s1 = 0.f, ss1 = 0.f;
                #pragma unroll
                for (int c = 0; c < 4; c++) {
                    ulonglong2 x0 = r0[c * 32 + lane];
                    ulonglong2 x1 = r1[c * 32 + lane];
                    if (doStats) {
                        float f0, f1, f2, f3;
                        unpack2(x0.x, f0, f1); unpack2(x0.y, f2, f3);
                        s0  += (f0 + f1) + (f2 + f3);
                        ss0 += f0*f0 + f1*f1 + f2*f2 + f3*f3;
                        unpack2(x1.x, f0, f1); unpack2(x1.y, f2, f3);
                        s1  += (f0 + f1) + (f2 + f3);
                        ss1 += f0*f0 + f1*f1 + f2*f2 + f3*f3;
                    }
                    #pragma unroll
                    for (int rr = 0; rr < 4; rr++) {
                        a[2*rr]   = fma2(x0.x, wR[rr][2*c],   a[2*rr]);
                        a[2*rr]   = fma2(x0.y, wR[rr][2*c+1], a[2*rr]);
                        a[2*rr+1] = fma2(x1.x, wR[rr][2*c],   a[2*rr+1]);
                        a[2*rr+1] = fma2(x1.y, wR[rr][2*c+1], a[2*rr+1]);
                    }
                }
                if (doStats) {
                    #pragma unroll
                    for (int o = 16; o; o >>= 1) {
                        s0  += __shfl_xor_sync(0xffffffffu, s0,  o);
                        ss0 += __shfl_xor_sync(0xffffffffu, ss0, o);
                        s1  += __shfl_xor_sync(0xffffffffu, s1,  o);
                        ss1 += __shfl_xor_sync(0xffffffffu, ss1, o);
                    }
                    if (lane == 0) {
                        float2* sp = (float2*)sstat + ((kc & 1) * 8 + p0) * 2 + dh;
                        sp[0] = make_float2(s0, ss0);
                        sp[2] = make_float2(s1, ss1);   // p1 slot = +2 float2
                    }
                }
                float v[8];
                #pragma unroll
                for (int i = 0; i < 8; i++) {
                    float lo, hi;
                    unpack2(a[i], lo, hi);
                    v[i] = lo + hi;
                }
                // packed tree: 8 dots -> lanes%4==0 in 9 shuffles
                float u2[4];
                #pragma unroll
                for (int i = 0; i < 4; i++) {
                    float xx = b16 ? v[2*i] : v[2*i+1];
                    float tt = __shfl_xor_sync(0xffffffffu, xx, 16);
                    u2[i] = (b16 ? v[2*i+1] : v[2*i]) + tt;
                }
                float q2[2];
                #pragma unroll
                for (int i = 0; i < 2; i++) {
                    float xx = b8 ? u2[2*i] : u2[2*i+1];
                    float tt = __shfl_xor_sync(0xffffffffu, xx, 8);
                    q2[i] = (b8 ? u2[2*i+1] : u2[2*i]) + tt;
                }
                float z;
                {
                    float xx = b4 ? q2[0] : q2[1];
                    float tt = __shfl_xor_sync(0xffffffffu, xx, 4);
                    z = (b4 ? q2[1] : q2[0]) + tt;
                }
                z += __shfl_xor_sync(0xffffffffu, z, 2);
                z += __shfl_xor_sync(0xffffffffu, z, 1);
                if ((lane & 3) == 0) {
                    int idx = ((lane >> 4) & 1) | ((lane >> 2) & 2) | (lane & 4);
                    int rr = idx >> 1, px = idx & 1;
                    int row = rbase + rr;
                    float* dst = dh ? scP : sc;
                    dst[row * 256 + kc * CH + p0 + px] = z;
                }
            }
            nbar_sync(1, 256);                 // D-internal: sc/scP/sstat done
            if (kc) nbar_sync(4, 512);         // Y done chunk kc-1

            // ---- online softmax for row srow ----
            {
                float vv = -1e30f, rs = 0.f, mv = 0.f;
                if (ok) {
                    int gp = kc * CH + pl;
                    float raw = sc[srow * 256 + gp] + scP[srow * 256 + gp];
                    const float2* sp = (const float2*)sstat + ((kc & 1) * 8 + pl) * 2;
                    float2 st0 = sp[0], st1 = sp[1];
                    float s = st0.x + st1.x, ss = st0.y + st1.y;
                    mv = s * (1.f / 1024.f);
                    rs = rsqrtf(ss * (1.f / 1024.f) - mv * mv + 1e-5f);
                    vv = fmaf(rs, raw, fmaf(-(rs * mv), gwS, sbS));
                    sc[srow * 256 + gp] = vv;   // corrected score for diversity
                }
                float c = vv;
                #pragma unroll
                for (int o = 8; o; o >>= 1)
                    c = fmaxf(c, __shfl_xor_sync(0xffffffffu, c, o));
                float mn = fmaxf(mO, c);
                float f = __expf(mO - mn);
                float e = ok ? __expf(vv - mn) : 0.f;
                float ar = e * rs;
                float su = e, cq = ar * mv;
                #pragma unroll
                for (int o = 8; o; o >>= 1) {
                    su += __shfl_xor_sync(0xffffffffu, su, o);
                    cq += __shfl_xor_sync(0xffffffffu, cq, o);
                }
                sO = sO * f + su;
                cpO = cpO * f + cq;
                mO = mn;
                if (ok) ar2c[(kc & 1) * 128 + pl * 16 + srow] = ar;
                if (pl == 0) f2s[(kc & 1) * 16 + srow] = f;
            }
            nbar_arrive(3, 512);               // chunk kc ready for Y
        }

        // ---- finalize state, signal Y, diversity ----
        if (pl == 0) {
            float is = 1.f / sO;
            invsr[srow] = is;
            ccrow[srow] = cpO * is;
            mrow[srow]  = mO;
        }
        nbar_sync(1, 256);
        nbar_arrive(5, 512);                   // state ready for Y epilogue

        if (w < 4) {
            const int n = w;
            float nrm = 0.f;
            #pragma unroll
            for (int i = 0; i < 8; i++) {
                int p = i * 32 + lane;
                float aa = 0.f;
                #pragma unroll
                for (int h = 0; h < 4; h++) {
                    int r = 4 * n + h;
                    aa += __expf(sc[r * 256 + p] - mrow[r]) * invsr[r];
                }
                aa *= 0.25f;
                av[n * 256 + p] = aa;
                nrm += aa * aa;
            }
            #pragma unroll
            for (int o = 16; o; o >>= 1) nrm += __shfl_xor_sync(0xffffffffu, nrm, o);
            if (lane == 0) avn[n] = 1.f / fmaxf(sqrtf(nrm), 1e-8f);
        }
        nbar_sync(1, 256);
        if (w < 6) {
            const int pi[6] = {0, 0, 0, 1, 1, 2};
            const int pj[6] = {1, 2, 3, 2, 3, 3};
            int i = pi[w], j = pj[w];
            float dt = 0.f;
            #pragma unroll
            for (int c = 0; c < 8; c++) {
                int p = c * 32 + lane;
                dt += av[i * 256 + p] * av[j * 256 + p];
            }
            #pragma unroll
            for (int o = 16; o; o >>= 1) dt += __shfl_xor_sync(0xffffffffu, dt, o);
            if (lane == 0) g_sims[bt * 6 + w] = dt * avn[i] * avn[j];
        }
    } else {
        // ============== GROUP Y: yacc + epilogue ==============
        const int t2 = t - 256;
        u64 yacc[8][4];
        #pragma unroll
        for (int q = 0; q < 8; q++)
            #pragma unroll
            for (int c = 0; c < 4; c++) yacc[q][c] = 0ull;

        for (int kc = 0; kc < NCH; kc++) {
            nbar_sync(3, 512);                 // ar2c/f2s/buf[kc%3] ready
            const float* fb = f2s + (kc & 1) * 16;
            #pragma unroll
            for (int q = 0; q < 8; q++) {
                u64 f2 = ((const u64*)fb)[q];
                #pragma unroll
                for (int c = 0; c < 4; c++) yacc[q][c] = mul2(yacc[q][c], f2);
            }
            const float4* xs4 = (const float4*)(buf + (kc % 3) * (CH * DV));
            const float* arb = ar2c + (kc & 1) * 128;
            #pragma unroll
            for (int lp = 0; lp < CH; lp++) {
                float4 xv = xs4[lp * 256 + t2];
                u64 xd0 = dup2(xv.x), xd1 = dup2(xv.y);
                u64 xd2 = dup2(xv.z), xd3 = dup2(xv.w);
                const ulonglong2* arp = (const ulonglong2*)(arb + lp * 16);
                #pragma unroll
                for (int qq = 0; qq < 4; qq++) {
                    ulonglong2 a2 = arp[qq];
                    yacc[2*qq][0]   = fma2(a2.x, xd0, yacc[2*qq][0]);
                    yacc[2*qq][1]   = fma2(a2.x, xd1, yacc[2*qq][1]);
                    yacc[2*qq][2]   = fma2(a2.x, xd2, yacc[2*qq][2]);
                    yacc[2*qq][3]   = fma2(a2.x, xd3, yacc[2*qq][3]);
                    yacc[2*qq+1][0] = fma2(a2.y, xd0, yacc[2*qq+1][0]);
                    yacc[2*qq+1][1] = fma2(a2.y, xd1, yacc[2*qq+1][1]);
                    yacc[2*qq+1][2] = fma2(a2.y, xd2, yacc[2*qq+1][2]);
                    yacc[2*qq+1][3] = fma2(a2.y, xd3, yacc[2*qq+1][3]);
                }
            }
            nbar_sync(2, 256);                 // Y-internal: buf drained
            if (t2 == 0 && kc + 3 < NCH) {
                mbar_expect(sbase + 8 * (kc % 3), CHBYTES);
                bulk_g2s(bufu + (kc % 3) * CHBYTES,
                         src + (size_t)(kc + 3) * CHBYTES, CHBYTES,
                         sbase + 8 * (kc % 3));
            }
            if (kc < NCH - 1) nbar_arrive(4, 512);  // release D / ar2c reuse
        }

        nbar_sync(5, 512);                     // wait invsr/ccrow from D

        // ---- epilogue: y = gamma*(yacc/s - cc) + beta -> g_y ----
        float4 g4 = ((const float4*)gamma)[t2];
        float4 b4 = ((const float4*)beta)[t2];
        u64 gd[4] = { dup2(g4.x), dup2(g4.y), dup2(g4.z), dup2(g4.w) };
        u64 bd[4] = { dup2(b4.x), dup2(b4.y), dup2(b4.z), dup2(b4.w) };
        #pragma unroll
        for (int q = 0; q < 8; q++) {
            u64 is2 = pack2(invsr[2*q], invsr[2*q+1]);
            u64 nc2 = pack2(-ccrow[2*q], -ccrow[2*q+1]);
            float lo[4], hi[4];
            #pragma unroll
            for (int c = 0; c < 4; c++) {
                u64 o = fma2(fma2(yacc[q][c], is2, nc2), gd[c], bd[c]);
                unpack2(o, lo[c], hi[c]);
            }
            ((float4*)(g_y + (size_t)((2*q)     * BT + bt) * DV))[t2] =
                make_float4(lo[0], lo[1], lo[2], lo[3]);
            ((float4*)(g_y + (size_t)((2*q + 1) * BT + bt) * DV))[t2] =
                make_float4(hi[0], hi[1], hi[2], hi[3]);
        }
    }
}

// =============================================================
// Kernel C v5: pooled = y @ Wv-slice + bv. (unchanged from R6)
// =============================================================
__global__ void __launch_bounds__(512, 1)
pooled_kernel(const float* __restrict__ Wv, const float* __restrict__ bv) {
    const int nh = blockIdx.x, btile = blockIdx.y;
    const int n = nh >> 2, h = nh & 3;
    __shared__ __align__(16) float wv_s[2][64 * 64];
    __shared__ __align__(16) float ys[2][16 * 66];
    __shared__ __align__(16) float red[256 * 4];
    const int t = threadIdx.x;
    const int btq = t & 15, jg = (t >> 4) & 15, ds = t >> 8;
    const int bt0 = btile * 16;
    const int dbase = ds * 32;

    const int wli_d0 = t >> 4, wli_c4 = t & 15;
    const int yb = t >> 5, yc = t & 31;

    float4 wr[2]; float2 yr;
    #define P_LOAD(KC) do { \
        wr[0] = *(const float4*)(Wv + ((size_t)(n * DV + (KC) * 64 + wli_d0)) * DB + h * 64 + wli_c4 * 4); \
        wr[1] = *(const float4*)(Wv + ((size_t)(n * DV + (KC) * 64 + wli_d0 + 32)) * DB + h * 64 + wli_c4 * 4); \
        yr = *(const float2*)(g_y + ((size_t)(nh * BT + bt0 + yb)) * DV + (KC) * 64 + yc * 2); \
    } while (0)
    #define P_STORE(B) do { \
        *(float4*)(wv_s[B] + wli_d0 * 64 + wli_c4 * 4) = wr[0]; \
        *(float4*)(wv_s[B] + (wli_d0 + 32) * 64 + wli_c4 * 4) = wr[1]; \
        *(float2*)(ys[B] + yb * 66 + yc * 2) = yr; \
    } while (0)

    P_LOAD(0); P_STORE(0); P_LOAD(1);
    __syncthreads();

    u64 acc0 = 0ull, acc1 = 0ull;

    for (int kc = 0; kc < 16; kc++) {
        const int cb = kc & 1;
        if (kc + 1 < 16) P_STORE((kc + 1) & 1);
        if (kc + 2 < 16) P_LOAD(kc + 2);

        const float* ysb = ys[cb] + btq * 66;
        const float* wvb = wv_s[cb];
        #pragma unroll 8
        for (int dd = 0; dd < 32; dd++) {
            const int d = dbase + dd;
            u64 y2 = dup2(ysb[d]);
            ulonglong2 w2 = *(const ulonglong2*)(wvb + d * 64 + jg * 4);
            acc0 = fma2(y2, w2.x, acc0);
            acc1 = fma2(y2, w2.y, acc1);
        }
        __syncthreads();
    }
    #undef P_LOAD
    #undef P_STORE

    if (ds == 1) {
        ((u64*)red)[(t - 256) * 2]     = acc0;
        ((u64*)red)[(t - 256) * 2 + 1] = acc1;
    }
    __syncthreads();
    if (ds == 0) {
        acc0 = add2(acc0, ((const u64*)red)[t * 2]);
        acc1 = add2(acc1, ((const u64*)red)[t * 2 + 1]);
        float a0, a1, a2, a3;
        unpack2(acc0, a0, a1);
        unpack2(acc1, a2, a3);
        const float* bvp = bv + n * DB + h * 64 + jg * 4;
        float4 o = make_float4(a0 + bvp[0], a1 + bvp[1], a2 + bvp[2], a3 + bvp[3]);
        *(float4*)(g_pooled + ((size_t)(n * BT + bt0 + btq)) * DB + h * 64 + jg * 4) = o;
    }
}

// =============================================================
// Kernel D v5: out = pooled @ Wo + bo. (unchanged from R6)
// =============================================================
__global__ void __launch_bounds__(512, 1)
out_kernel(const float* __restrict__ Wo, const float* __restrict__ bo,
           float* __restrict__ out) {
    const int n = blockIdx.x, bt0 = blockIdx.y * 4;
    __shared__ __align__(16) float ps[4 * 260];
    __shared__ __align__(16) float ws[2][16 * 256];
    const int t = threadIdx.x;
    const int btq = t & 3, mq = t >> 2;

    *(float2*)(ps + (t >> 7) * 260 + (t & 127) * 2) =
        *(const float2*)(g_pooled + ((size_t)(n * BT + bt0 + (t >> 7))) * DB + (t & 127) * 2);

    const int wk0 = t >> 6, wc4 = t & 63;
    float4 wr[2];
    #define O_LOAD(KC) do { \
        wr[0] = *(const float4*)(Wo + ((size_t)(n * DB + (KC) * 16 + wk0)) * DB + wc4 * 4); \
        wr[1] = *(const float4*)(Wo + ((size_t)(n * DB + (KC) * 16 + wk0 + 8)) * DB + wc4 * 4); \
    } while (0)
    #define O_STORE(B) do { \
        *(float4*)(ws[B] + wk0 * 256 + wc4 * 4) = wr[0]; \
        *(float4*)(ws[B] + (wk0 + 8) * 256 + wc4 * 4) = wr[1]; \
    } while (0)

    O_LOAD(0); O_STORE(0); O_LOAD(1);
    __syncthreads();

    u64 accA = 0ull, accB = 0ull;

    for (int kc = 0; kc < 16; kc++) {
        const int cb = kc & 1;
        if (kc + 1 < 16) O_STORE((kc + 1) & 1);
        if (kc + 2 < 16) O_LOAD(kc + 2);

        const float* psb = ps + btq * 260 + kc * 16;
        const float* wsb = ws[cb];
        #pragma unroll
        for (int k = 0; k < 16; k += 2) {
            u64 pA = dup2(psb[k]);
            u64 pB = dup2(psb[k + 1]);
            accA = fma2(pA, *(const u64*)(wsb + k * 256 + mq * 2), accA);
            accB = fma2(pB, *(const u64*)(wsb + (k + 1) * 256 + mq * 2), accB);
        }
        __syncthreads();
    }
    #undef O_LOAD
    #undef O_STORE

    u64 acc = add2(accA, accB);
    float a0, a1;
    unpack2(acc, a0, a1);
    const int m = mq * 2;
    const float* bop = bo + n * DB + m;
    float2 o = make_float2(a0 + bop[0], a1 + bop[1]);
    *(float2*)(out + ((size_t)(bt0 + btq) * 4 + n) * DB + m) = o;
}

// =============================================================
// Kernel E: diversity loss finalize
// =============================================================
__global__ void loss_kernel(float* __restrict__ out) {
    __shared__ float part[6];
    const int t = threadIdx.x;
    if (t < 6) {
        float s = 0.f;
        for (int b = 0; b < BT; b++) s += g_sims[b * 6 + t];
        part[t] = s;
    }
    __syncthreads();
    if (t == 0) {
        float tot = part[0] + part[1] + part[2] + part[3] + part[4] + part[5];
        out[0] = 0.1f * (tot * (1.f / 128.f)) * (1.f / 6.f);
    }
}

// =============================================================
extern "C" void kernel_launch(void* const* d_in, const int* in_sizes, int n_in,
                              void* d_out, int out_size) {
    const float* frame = (const float*)d_in[0];
    const float* gam   = (const float*)d_in[1];
    const float* bet   = (const float*)d_in[2];
    const float* query = (const float*)d_in[3];
    const float* Wk    = (const float*)d_in[4];
    const float* bk    = (const float*)d_in[5];
    const float* Wv    = (const float*)d_in[6];
    const float* bv    = (const float*)d_in[7];
    const float* Wo    = (const float*)d_in[8];
    const float* bo    = (const float*)d_in[9];
    float* out = (float*)d_out;

    prep_kernel<<<16, 256>>>(Wk, query, bk, gam, bet);

    cudaFuncSetAttribute(main_kernel, cudaFuncAttributeMaxDynamicSharedMemorySize,
                         SMEM_MAIN_BYTES);
    main_kernel<<<128, 512, SMEM_MAIN_BYTES>>>(frame, gam, bet);

    pooled_kernel<<<dim3(16, 8), 512>>>(Wv, bv);
    out_kernel<<<dim3(4, 32), 512>>>(Wo, bo, out);

    if (out_size > BT * NBR * DB)
        loss_kernel<<<1, 32>>>(out + (size_t)BT * NBR * DB);
}

// round 8
// speedup vs baseline: 1.1215x; 1.1215x over previous
#include <cuda_runtime.h>
#include <math.h>
#include <stdint.h>

// Problem constants
#define BT   128          // B*T
#define NP   256          // patches
#define DV   1024         // D_VISION
#define NHD  16           // N_BRANCHES * N_HEADS
#define NBR  4
#define DB   256          // D_BRANCH
#define SCALE 0.125f      // HEAD_DIM^-0.5

#define CH    16          // patches per chunk (main kernel)
#define NCH   16          // chunks per bt
#define CHBYTES (CH * DV * 4)   // 65536

typedef unsigned long long u64;

// -------- device scratch (no allocation allowed) --------
__device__ __align__(16) float g_wqg[NHD * DV];
__device__ __align__(16) float2 g_prep[NHD * 8];   // per (nh, slice) partial (gw, bw[+bq])
__device__ __align__(16) float g_y[(size_t)NHD * BT * DV];   // 8 MB
__device__ __align__(16) float g_pooled[NBR * BT * DB];
__device__ float g_sims[BT * 6];

// ---------------- f32x2 helpers ----------------
__device__ __forceinline__ u64 fma2(u64 a, u64 b, u64 c) {
    u64 d;
    asm("fma.rn.f32x2 %0, %1, %2, %3;" : "=l"(d) : "l"(a), "l"(b), "l"(c));
    return d;
}
__device__ __forceinline__ u64 mul2(u64 a, u64 b) {
    u64 d;
    asm("mul.rn.f32x2 %0, %1, %2;" : "=l"(d) : "l"(a), "l"(b));
    return d;
}
__device__ __forceinline__ u64 add2(u64 a, u64 b) {
    u64 d;
    asm("add.rn.f32x2 %0, %1, %2;" : "=l"(d) : "l"(a), "l"(b));
    return d;
}
__device__ __forceinline__ u64 dup2(float v) {
    u64 r;
    asm("mov.b64 %0, {%1, %1};" : "=l"(r) : "f"(v));
    return r;
}
__device__ __forceinline__ u64 pack2(float lo, float hi) {
    u64 r;
    asm("mov.b64 %0, {%1, %2};" : "=l"(r) : "f"(lo), "f"(hi));
    return r;
}
__device__ __forceinline__ void unpack2(u64 v, float& lo, float& hi) {
    asm("mov.b64 {%0, %1}, %2;" : "=f"(lo), "=f"(hi) : "l"(v));
}

// packed 8-value warp reduction tree: returns per-lane combined value;
// lanes with lane%4==0 hold sum-over-warp of v[idx],
// idx = ((lane>>4)&1) | ((lane>>2)&2) | (lane&4)
__device__ __forceinline__ float tree8(const float v[8], bool b16, bool b8, bool b4) {
    float u2[4];
    #pragma unroll
    for (int i = 0; i < 4; i++) {
        float xx = b16 ? v[2*i] : v[2*i+1];
        float tt = __shfl_xor_sync(0xffffffffu, xx, 16);
        u2[i] = (b16 ? v[2*i+1] : v[2*i]) + tt;
    }
    float q2[2];
    #pragma unroll
    for (int i = 0; i < 2; i++) {
        float xx = b8 ? u2[2*i] : u2[2*i+1];
        float tt = __shfl_xor_sync(0xffffffffu, xx, 8);
        q2[i] = (b8 ? u2[2*i+1] : u2[2*i]) + tt;
    }
    float z;
    {
        float xx = b4 ? q2[0] : q2[1];
        float tt = __shfl_xor_sync(0xffffffffu, xx, 4);
        z = (b4 ? q2[1] : q2[0]) + tt;
    }
    z += __shfl_xor_sync(0xffffffffu, z, 2);
    z += __shfl_xor_sync(0xffffffffu, z, 1);
    return z;
}

// ---------------- sync / bulk-copy helpers ----------------
__device__ __forceinline__ uint32_t smem_u32(const void* p) {
    uint32_t a;
    asm("{ .reg .u64 t; cvta.to.shared.u64 t, %1; cvt.u32.u64 %0, t; }"
        : "=r"(a) : "l"(p));
    return a;
}
__device__ __forceinline__ void mbar_init(uint32_t mbar, uint32_t count) {
    asm volatile("mbarrier.init.shared.b64 [%0], %1;" :: "r"(mbar), "r"(count) : "memory");
}
__device__ __forceinline__ void mbar_expect(uint32_t mbar, uint32_t bytes) {
    asm volatile("mbarrier.arrive.expect_tx.shared.b64 _, [%0], %1;"
                 :: "r"(mbar), "r"(bytes) : "memory");
}
__device__ __forceinline__ void mbar_wait(uint32_t mbar, int phase) {
    asm volatile(
        "{\n\t.reg .pred P;\n\t"
        "WL_%=:\n\t"
        "mbarrier.try_wait.parity.acquire.cta.shared::cta.b64 P, [%0], %1, 0x989680;\n\t"
        "@P bra.uni WD_%=;\n\t"
        "bra.uni WL_%=;\n\t"
        "WD_%=:\n\t}"
        :: "r"(mbar), "r"(phase) : "memory");
}
__device__ __forceinline__ void bulk_g2s(uint32_t dst, const void* src,
                                         uint32_t bytes, uint32_t mbar) {
    asm volatile(
        "cp.async.bulk.shared::cluster.global.mbarrier::complete_tx::bytes [%0], [%1], %2, [%3];"
        :: "r"(dst), "l"(src), "r"(bytes), "r"(mbar) : "memory");
}

// =============================================================
// Kernel A v2: fold query into Wk.  grid (16 nh, 8 d-slices), 128 thr.
// Writes g_wqg slice + per-slice partial (gw, bw[+bq]) -> g_prep.
// =============================================================
__global__ void __launch_bounds__(128, 1)
prep_kernel(const float* __restrict__ Wk,
            const float* __restrict__ query,
            const float* __restrict__ bk,
            const float* __restrict__ gamma,
            const float* __restrict__ beta) {
    const int nh = blockIdx.x, slice = blockIdx.y;
    const int n = nh >> 2, h = nh & 3;
    __shared__ float q_s[64];
    __shared__ float r1[128], r2[128];
    const int t = threadIdx.x;
    if (t < 64) q_s[t] = query[nh * 64 + t];
    __syncthreads();

    const int d = slice * 128 + t;
    const float4* qq = (const float4*)q_s;
    const float4* w4 = (const float4*)(Wk + ((size_t)(n * DV + d)) * DB + h * 64);
    float s = 0.f;
    #pragma unroll
    for (int j = 0; j < 16; j++) {
        float4 a = w4[j]; float4 b = qq[j];
        s += a.x * b.x + a.y * b.y + a.z * b.z + a.w * b.w;
    }
    g_wqg[nh * DV + d] = SCALE * gamma[d] * s;
    r1[t] = gamma[d] * s;
    r2[t] = beta[d] * s;
    __syncthreads();
    for (int o = 64; o; o >>= 1) {
        if (t < o) { r1[t] += r1[t + o]; r2[t] += r2[t + o]; }
        __syncthreads();
    }
    if (t == 0) {
        float bq = 0.f;
        if (slice == 0)
            for (int j = 0; j < 64; j++) bq += bk[n * DB + h * 64 + j] * q_s[j];
        g_prep[nh * 8 + slice] = make_float2(r1[0], r2[0] + bq);
    }
}

// =============================================================
// Kernel B v8: single-pass main, 256 threads / 8 warps, d-split dots.
//  dots: warp w -> rg=w&1 (8 rows: rg*8..+8), dh=(w>>1)&1 (d-half),
//        pq=w>>2 (8 patches). x multiplicity in smem = 2 (was 4).
//  LN stats: warp computes d-half stats for patches pq*8+rg*4..+4,
//        batch-reduced in one tree8; combined in softmax phase.
//  softmax: warp w -> rows 2w (lanes 0-15), 2w+1 (lanes 16-31).
//  yacc: thread owns 4 cols; rows packed pairwise into u64 lanes.
// =============================================================
// smem floats:
//  0 mbar(4) | 4 f2s[16] | 20 mrow[16] | 36 invsr[16] | 52 ccrow[16]
//  68 avn[4] | 72 s_gw[16] | 88 s_scb[16] | 104 pad -> 112
//  112 sstat[64] | 176 ar2c[256] | 432 av[1024] -> 1456
//  1456 sc[16*257=4112] -> 5568 | 5568 scP[16*17=272] -> 5840
//  5840 buf[2][16384] -> 38608
#define SMEM_MAIN_FLOATS 38608
#define SMEM_MAIN_BYTES  (SMEM_MAIN_FLOATS * 4)

__global__ void __launch_bounds__(256, 1)
main_kernel(const float* __restrict__ frame,
            const float* __restrict__ gamma,
            const float* __restrict__ beta) {
    extern __shared__ float smf[];
    float* f2s   = smf + 4;
    float* mrow  = smf + 20;
    float* invsr = smf + 36;
    float* ccrow = smf + 52;
    float* avn   = smf + 68;
    float* s_gw  = smf + 72;
    float* s_scb = smf + 88;
    float* sstat = smf + 112;   // [patch 16][val 2][dh 2]
    float* ar2c  = smf + 176;   // [patch 16][row 16]
    float* av    = smf + 432;
    float* sc    = smf + 1456;  // [16][257]
    float* scP   = smf + 5568;  // [16][17]
    float* buf   = smf + 5840;  // [2][16384]

    const int t = threadIdx.x, w = t >> 5, lane = t & 31;
    const int bt = blockIdx.x;
    const uint32_t sbase = smem_u32(smf);
    const uint32_t mbar0 = sbase, mbar1 = sbase + 8;
    const uint32_t bufu = smem_u32(buf);

    const int rg = w & 1, dh = (w >> 1) & 1, pq = w >> 2;

    // folded-query weights: 8 rows x 512 d (this warp's d-half) = 128 regs
    u64 wR[8][8];
    #pragma unroll
    for (int rr = 0; rr < 8; rr++) {
        const ulonglong2* wp =
            (const ulonglong2*)(g_wqg + (rg * 8 + rr) * DV + dh * 512);
        #pragma unroll
        for (int c = 0; c < 4; c++) {
            ulonglong2 v = wp[c * 32 + lane];
            wR[rr][2*c] = v.x; wR[rr][2*c+1] = v.y;
        }
    }

    // finalize prep partials -> s_gw/s_scb
    if (t < 16) {
        float a = 0.f, b2 = 0.f;
        #pragma unroll
        for (int s2 = 0; s2 < 8; s2++) {
            float2 v = g_prep[t * 8 + s2];
            a += v.x; b2 += v.y;
        }
        s_gw[t]  = SCALE * a;
        s_scb[t] = SCALE * b2;
    }
    if (t == 0) { mbar_init(mbar0, 1); mbar_init(mbar1, 1); }
    __syncthreads();

    const char* src = (const char*)(frame + (size_t)bt * NP * DV);
    if (t == 0) {
        mbar_expect(mbar0, CHBYTES);
        bulk_g2s(bufu, src, CHBYTES, mbar0);
        mbar_expect(mbar1, CHBYTES);
        bulk_g2s(bufu + CHBYTES, src + CHBYTES, CHBYTES, mbar1);
    }

    // yacc: thread owns cols 4t..4t+3; rows packed pairwise (8 pairs)
    u64 yacc[8][4];
    #pragma unroll
    for (int q = 0; q < 8; q++)
        #pragma unroll
        for (int c = 0; c < 4; c++) yacc[q][c] = 0ull;

    const int half = lane >> 4, srow = 2 * w + half, pl = lane & 15;
    const float gwS = s_gw[srow], sbS = s_scb[srow];
    float mO = -1e30f, sO = 0.f, cpO = 0.f;

    const bool b16 = (lane & 16) != 0;
    const bool b8  = (lane & 8)  != 0;
    const bool b4  = (lane & 4)  != 0;

    for (int kc = 0; kc < NCH; kc++) {
        const int b = kc & 1;
        const uint32_t mb = b ? mbar1 : mbar0;
        mbar_wait(mb, (kc >> 1) & 1);
        float* xb = buf + b * (CH * DV);

        // ---- dots (d-half) + fused LN partial stats ----
        {
            const ulonglong2* x2 = (const ulonglong2*)xb;
            float st_s[4], st_ss[4];
            #pragma unroll
            for (int j = 0; j < 4; j++) { st_s[j] = 0.f; st_ss[j] = 0.f; }

            #pragma unroll
            for (int pi = 0; pi < 8; pi++) {
                const int p = pq * 8 + pi;
                const ulonglong2* r0 = x2 + p * 256 + dh * 128;
                const bool doStats = ((pi >> 2) == rg);
                u64 a[8];
                #pragma unroll
                for (int i = 0; i < 8; i++) a[i] = 0ull;
                float s_acc = 0.f, ss_acc = 0.f;
                #pragma unroll
                for (int c = 0; c < 4; c++) {
                    ulonglong2 xv = r0[c * 32 + lane];
                    if (doStats) {
                        float f0, f1, f2, f3;
                        unpack2(xv.x, f0, f1); unpack2(xv.y, f2, f3);
                        s_acc  += (f0 + f1) + (f2 + f3);
                        ss_acc += f0*f0 + f1*f1 + f2*f2 + f3*f3;
                    }
                    #pragma unroll
                    for (int rr = 0; rr < 8; rr++) {
                        a[rr] = fma2(xv.x, wR[rr][2*c],   a[rr]);
                        a[rr] = fma2(xv.y, wR[rr][2*c+1], a[rr]);
                    }
                }
                if (doStats) { st_s[pi & 3] = s_acc; st_ss[pi & 3] = ss_acc; }

                float v[8];
                #pragma unroll
                for (int i = 0; i < 8; i++) {
                    float lo, hi;
                    unpack2(a[i], lo, hi);
                    v[i] = lo + hi;
                }
                float z = tree8(v, b16, b8, b4);
                if ((lane & 3) == 0) {
                    int idx = ((lane >> 4) & 1) | ((lane >> 2) & 2) | (lane & 4);
                    int row = rg * 8 + idx;
                    if (dh == 0) sc[row * 257 + kc * CH + p] = z;
                    else         scP[row * 17 + p] = z;
                }
            }

            // batch stats tree: v = {s0,ss0,s1,ss1,s2,ss2,s3,ss3}
            {
                float v[8];
                #pragma unroll
                for (int j = 0; j < 4; j++) { v[2*j] = st_s[j]; v[2*j+1] = st_ss[j]; }
                float z = tree8(v, b16, b8, b4);
                if ((lane & 3) == 0) {
                    int idx = ((lane >> 4) & 1) | ((lane >> 2) & 2) | (lane & 4);
                    int is_ss = idx & 1, j = idx >> 1;
                    int p = pq * 8 + rg * 4 + j;
                    sstat[p * 4 + is_ss * 2 + dh] = z;
                }
            }
        }
        __syncthreads();

        // ---- online softmax: combine halves + LN correction ----
        {
            int gp = kc * CH + pl;
            float raw = sc[srow * 257 + gp] + scP[srow * 17 + pl];
            float s  = sstat[pl * 4 + 0] + sstat[pl * 4 + 1];
            float ss = sstat[pl * 4 + 2] + sstat[pl * 4 + 3];
            float mv = s * (1.f / 1024.f);
            float rs = rsqrtf(ss * (1.f / 1024.f) - mv * mv + 1e-5f);
            float vv = fmaf(rs, raw, fmaf(-(rs * mv), gwS, sbS));
            sc[srow * 257 + gp] = vv;          // corrected score (diversity)
            float c = vv;
            #pragma unroll
            for (int o = 8; o; o >>= 1)
                c = fmaxf(c, __shfl_xor_sync(0xffffffffu, c, o));
            float mn = fmaxf(mO, c);
            float f = __expf(mO - mn);
            float e = __expf(vv - mn);
            float ar = e * rs;
            float su = e, cq = ar * mv;
            #pragma unroll
            for (int o = 8; o; o >>= 1) {
                su += __shfl_xor_sync(0xffffffffu, su, o);
                cq += __shfl_xor_sync(0xffffffffu, cq, o);
            }
            sO = sO * f + su;
            cpO = cpO * f + cq;
            mO = mn;
            ar2c[pl * 16 + srow] = ar;
            if (pl == 0) f2s[srow] = f;
        }
        __syncthreads();

        // ---- yacc rescale + accumulate (4 cols/thread) ----
        {
            #pragma unroll
            for (int q = 0; q < 8; q++) {
                u64 f2 = ((const u64*)f2s)[q];
                #pragma unroll
                for (int c = 0; c < 4; c++) yacc[q][c] = mul2(yacc[q][c], f2);
            }
            const float4* xs4 = (const float4*)xb;
            #pragma unroll 2
            for (int lp = 0; lp < CH; lp++) {
                float4 xv = xs4[lp * 256 + t];
                u64 xd0 = dup2(xv.x), xd1 = dup2(xv.y);
                u64 xd2 = dup2(xv.z), xd3 = dup2(xv.w);
                const ulonglong2* arp = (const ulonglong2*)(ar2c + lp * 16);
                #pragma unroll
                for (int qq = 0; qq < 4; qq++) {
                    ulonglong2 a2 = arp[qq];
                    yacc[2*qq][0]   = fma2(a2.x, xd0, yacc[2*qq][0]);
                    yacc[2*qq][1]   = fma2(a2.x, xd1, yacc[2*qq][1]);
                    yacc[2*qq][2]   = fma2(a2.x, xd2, yacc[2*qq][2]);
                    yacc[2*qq][3]   = fma2(a2.x, xd3, yacc[2*qq][3]);
                    yacc[2*qq+1][0] = fma2(a2.y, xd0, yacc[2*qq+1][0]);
                    yacc[2*qq+1][1] = fma2(a2.y, xd1, yacc[2*qq+1][1]);
                    yacc[2*qq+1][2] = fma2(a2.y, xd2, yacc[2*qq+1][2]);
                    yacc[2*qq+1][3] = fma2(a2.y, xd3, yacc[2*qq+1][3]);
                }
            }
        }
        __syncthreads();   // buffer b free

        if (t == 0 && kc + 2 < NCH) {
            mbar_expect(mb, CHBYTES);
            bulk_g2s(bufu + b * CHBYTES, src + (size_t)(kc + 2) * CHBYTES, CHBYTES, mb);
        }
    }

    // ---- finalize per-row softmax state ----
    if (pl == 0) {
        float is = 1.f / sO;
        invsr[srow] = is;
        ccrow[srow] = cpO * is;
        mrow[srow]  = mO;
    }
    __syncthreads();

    // ---- epilogue: y = gamma*(yacc/s - cc) + beta -> g_y ----
    {
        float4 g4 = ((const float4*)gamma)[t];
        float4 b4 = ((const float4*)beta)[t];
        u64 gd[4] = { dup2(g4.x), dup2(g4.y), dup2(g4.z), dup2(g4.w) };
        u64 bd[4] = { dup2(b4.x), dup2(b4.y), dup2(b4.z), dup2(b4.w) };
        #pragma unroll
        for (int q = 0; q < 8; q++) {
            u64 is2 = pack2(invsr[2*q], invsr[2*q+1]);
            u64 nc2 = pack2(-ccrow[2*q], -ccrow[2*q+1]);
            float lo[4], hi[4];
            #pragma unroll
            for (int c = 0; c < 4; c++) {
                u64 o = fma2(fma2(yacc[q][c], is2, nc2), gd[c], bd[c]);
                unpack2(o, lo[c], hi[c]);
            }
            ((float4*)(g_y + (size_t)((2*q)     * BT + bt) * DV))[t] =
                make_float4(lo[0], lo[1], lo[2], lo[3]);
            ((float4*)(g_y + (size_t)((2*q + 1) * BT + bt) * DV))[t] =
                make_float4(hi[0], hi[1], hi[2], hi[3]);
        }
    }

    // ---- diversity partials (recompute attn from corrected scores) ----
    if (w < 4) {
        const int n = w;
        float nrm = 0.f;
        #pragma unroll
        for (int i = 0; i < 8; i++) {
            int p = i * 32 + lane;
            float aa = 0.f;
            #pragma unroll
            for (int h = 0; h < 4; h++) {
                int r = 4 * n + h;
                aa += __expf(sc[r * 257 + p] - mrow[r]) * invsr[r];
            }
            aa *= 0.25f;
            av[n * 256 + p] = aa;
            nrm += aa * aa;
        }
        #pragma unroll
        for (int o = 16; o; o >>= 1) nrm += __shfl_xor_sync(0xffffffffu, nrm, o);
        if (lane == 0) avn[n] = 1.f / fmaxf(sqrtf(nrm), 1e-8f);
    }
    __syncthreads();
    if (w < 6) {
        const int pi[6] = {0, 0, 0, 1, 1, 2};
        const int pj[6] = {1, 2, 3, 2, 3, 3};
        int i = pi[w], j = pj[w];
        float dt = 0.f;
        #pragma unroll
        for (int c = 0; c < 8; c++) {
            int p = c * 32 + lane;
            dt += av[i * 256 + p] * av[j * 256 + p];
        }
        #pragma unroll
        for (int o = 16; o; o >>= 1) dt += __shfl_xor_sync(0xffffffffu, dt, o);
        if (lane == 0) g_sims[bt * 6 + w] = dt * avn[i] * avn[j];
    }
}

// =============================================================
// Kernel C: pooled = y @ Wv-slice + bv. (unchanged from R6)
// =============================================================
__global__ void __launch_bounds__(512, 1)
pooled_kernel(const float* __restrict__ Wv, const float* __restrict__ bv) {
    const int nh = blockIdx.x, btile = blockIdx.y;
    const int n = nh >> 2, h = nh & 3;
    __shared__ __align__(16) float wv_s[2][64 * 64];
    __shared__ __align__(16) float ys[2][16 * 66];
    __shared__ __align__(16) float red[256 * 4];
    const int t = threadIdx.x;
    const int btq = t & 15, jg = (t >> 4) & 15, ds = t >> 8;
    const int bt0 = btile * 16;
    const int dbase = ds * 32;

    const int wli_d0 = t >> 4, wli_c4 = t & 15;
    const int yb = t >> 5, yc = t & 31;

    float4 wr[2]; float2 yr;
    #define P_LOAD(KC) do { \
        wr[0] = *(const float4*)(Wv + ((size_t)(n * DV + (KC) * 64 + wli_d0)) * DB + h * 64 + wli_c4 * 4); \
        wr[1] = *(const float4*)(Wv + ((size_t)(n * DV + (KC) * 64 + wli_d0 + 32)) * DB + h * 64 + wli_c4 * 4); \
        yr = *(const float2*)(g_y + ((size_t)(nh * BT + bt0 + yb)) * DV + (KC) * 64 + yc * 2); \
    } while (0)
    #define P_STORE(B) do { \
        *(float4*)(wv_s[B] + wli_d0 * 64 + wli_c4 * 4) = wr[0]; \
        *(float4*)(wv_s[B] + (wli_d0 + 32) * 64 + wli_c4 * 4) = wr[1]; \
        *(float2*)(ys[B] + yb * 66 + yc * 2) = yr; \
    } while (0)

    P_LOAD(0); P_STORE(0); P_LOAD(1);
    __syncthreads();

    u64 acc0 = 0ull, acc1 = 0ull;

    for (int kc = 0; kc < 16; kc++) {
        const int cb = kc & 1;
        if (kc + 1 < 16) P_STORE((kc + 1) & 1);
        if (kc + 2 < 16) P_LOAD(kc + 2);

        const float* ysb = ys[cb] + btq * 66;
        const float* wvb = wv_s[cb];
        #pragma unroll 8
        for (int dd = 0; dd < 32; dd++) {
            const int d = dbase + dd;
            u64 y2 = dup2(ysb[d]);
            ulonglong2 w2 = *(const ulonglong2*)(wvb + d * 64 + jg * 4);
            acc0 = fma2(y2, w2.x, acc0);
            acc1 = fma2(y2, w2.y, acc1);
        }
        __syncthreads();
    }
    #undef P_LOAD
    #undef P_STORE

    if (ds == 1) {
        ((u64*)red)[(t - 256) * 2]     = acc0;
        ((u64*)red)[(t - 256) * 2 + 1] = acc1;
    }
    __syncthreads();
    if (ds == 0) {
        acc0 = add2(acc0, ((const u64*)red)[t * 2]);
        acc1 = add2(acc1, ((const u64*)red)[t * 2 + 1]);
        float a0, a1, a2, a3;
        unpack2(acc0, a0, a1);
        unpack2(acc1, a2, a3);
        const float* bvp = bv + n * DB + h * 64 + jg * 4;
        float4 o = make_float4(a0 + bvp[0], a1 + bvp[1], a2 + bvp[2], a3 + bvp[3]);
        *(float4*)(g_pooled + ((size_t)(n * BT + bt0 + btq)) * DB + h * 64 + jg * 4) = o;
    }
}

// =============================================================
// Kernel D: out = pooled @ Wo + bo (+ fused diversity-loss finalize)
// =============================================================
__global__ void __launch_bounds__(512, 1)
out_kernel(const float* __restrict__ Wo, const float* __restrict__ bo,
           float* __restrict__ out, float* __restrict__ lossout) {
    const int n = blockIdx.x, bt0 = blockIdx.y * 4;
    __shared__ __align__(16) float ps[4 * 260];
    __shared__ __align__(16) float ws[2][16 * 256];
    const int t = threadIdx.x;
    const int btq = t & 3, mq = t >> 2;

    *(float2*)(ps + (t >> 7) * 260 + (t & 127) * 2) =
        *(const float2*)(g_pooled + ((size_t)(n * BT + bt0 + (t >> 7))) * DB + (t & 127) * 2);

    const int wk0 = t >> 6, wc4 = t & 63;
    float4 wr[2];
    #define O_LOAD(KC) do { \
        wr[0] = *(const float4*)(Wo + ((size_t)(n * DB + (KC) * 16 + wk0)) * DB + wc4 * 4); \
        wr[1] = *(const float4*)(Wo + ((size_t)(n * DB + (KC) * 16 + wk0 + 8)) * DB + wc4 * 4); \
    } while (0)
    #define O_STORE(B) do { \
        *(float4*)(ws[B] + wk0 * 256 + wc4 * 4) = wr[0]; \
        *(float4*)(ws[B] + (wk0 + 8) * 256 + wc4 * 4) = wr[1]; \
    } while (0)

    O_LOAD(0); O_STORE(0); O_LOAD(1);
    __syncthreads();

    u64 accA = 0ull, accB = 0ull;

    for (int kc = 0; kc < 16; kc++) {
        const int cb = kc & 1;
        if (kc + 1 < 16) O_STORE((kc + 1) & 1);
        if (kc + 2 < 16) O_LOAD(kc + 2);

        const float* psb = ps + btq * 260 + kc * 16;
        const float* wsb = ws[cb];
        #pragma unroll
        for (int k = 0; k < 16; k += 2) {
            u64 pA = dup2(psb[k]);
            u64 pB = dup2(psb[k + 1]);
            accA = fma2(pA, *(const u64*)(wsb + k * 256 + mq * 2), accA);
            accB = fma2(pB, *(const u64*)(wsb + (k + 1) * 256 + mq * 2), accB);
        }
        __syncthreads();
    }
    #undef O_LOAD
    #undef O_STORE

    u64 acc = add2(accA, accB);
    float a0, a1;
    unpack2(acc, a0, a1);
    const int m = mq * 2;
    const float* bop = bo + n * DB + m;
    float2 o = make_float2(a0 + bop[0], a1 + bop[1]);
    *(float2*)(out + ((size_t)(bt0 + btq) * 4 + n) * DB + m) = o;

    // ---- fused diversity-loss finalize (one warp of one block) ----
    if (lossout != nullptr && blockIdx.x == 0 && blockIdx.y == 0 && t < 32) {
        float tot = 0.f;
        #pragma unroll
        for (int pr = 0; pr < 6; pr++) {
            float s = 0.f;
            for (int b = t; b < BT; b += 32) s += g_sims[b * 6 + pr];
            #pragma unroll
            for (int oo = 16; oo; oo >>= 1)
                s += __shfl_xor_sync(0xffffffffu, s, oo);
            tot += s;
        }
        if (t == 0) lossout[0] = 0.1f * (tot * (1.f / 128.f)) * (1.f / 6.f);
    }
}

// =============================================================
extern "C" void kernel_launch(void* const* d_in, const int* in_sizes, int n_in,
                              void* d_out, int out_size) {
    const float* frame = (const float*)d_in[0];
    const float* gam   = (const float*)d_in[1];
    const float* bet   = (const float*)d_in[2];
    const float* query = (const float*)d_in[3];
    const float* Wk    = (const float*)d_in[4];
    const float* bk    = (const float*)d_in[5];
    const float* Wv    = (const float*)d_in[6];
    const float* bv    = (const float*)d_in[7];
    const float* Wo    = (const float*)d_in[8];
    const float* bo    = (const float*)d_in[9];
    float* out = (float*)d_out;

    prep_kernel<<<dim3(16, 8), 128>>>(Wk, query, bk, gam, bet);

    cudaFuncSetAttribute(main_kernel, cudaFuncAttributeMaxDynamicSharedMemorySize,
                         SMEM_MAIN_BYTES);
    main_kernel<<<128, 256, SMEM_MAIN_BYTES>>>(frame, gam, bet);

    pooled_kernel<<<dim3(16, 8), 512>>>(Wv, bv);

    float* lossout = (out_size > BT * NBR * DB) ? out + (size_t)BT * NBR * DB : nullptr;
    out_kernel<<<dim3(4, 32), 512>>>(Wo, bo, out, lossout);
}